// round 1
// baseline (speedup 1.0000x reference)
#include <cuda_runtime.h>
#include <cuda_bf16.h>
#include <cstdint>

// Problem constants
#define NROIS 1000
#define CCH   192
#define KDIM  9408   // 192*49
#define DDIM  768
#define MN    (NROIS*DDIM)
#define KSPLIT 4

// Scratch (device globals; no allocation allowed)
__device__ float g_pooled[NROIS * KDIM];          // [n][c*49+i*7+j]
__device__ float g_part[KSPLIT * NROIS * DDIM];   // split-K partials
__device__ float g_x1[NROIS * DDIM];
__device__ float g_x2[NROIS * DDIM];

// ---------------------------------------------------------------------------
// f32x2 packed FMA helpers (sm_100+: fma.rn.f32x2)
// ---------------------------------------------------------------------------
__device__ __forceinline__ unsigned long long pack2(float x, float y) {
    unsigned long long r;
    asm("mov.b64 %0, {%1, %2};" : "=l"(r) : "f"(x), "f"(y));
    return r;
}
__device__ __forceinline__ void fma2(unsigned long long& d, unsigned long long a, unsigned long long b) {
    asm("fma.rn.f32x2 %0, %1, %2, %0;" : "+l"(d) : "l"(a), "l"(b));
}
__device__ __forceinline__ float2 unpack2(unsigned long long v) {
    float lo, hi;
    asm("mov.b64 {%0, %1}, %2;" : "=f"(lo), "=f"(hi) : "l"(v));
    return make_float2(lo, hi);
}

// ---------------------------------------------------------------------------
// Kernel 1: pyramid RoIAlign. 1 block per ROI, 192 threads = channels.
// Writes g_pooled[n][c*49 + i*7 + j] (matches w1 (o,c,i,j) flattening).
// ---------------------------------------------------------------------------
__global__ __launch_bounds__(192) void roi_align_kernel(
    const float* __restrict__ f0, const float* __restrict__ f1,
    const float* __restrict__ f2, const float* __restrict__ f3,
    const float* __restrict__ rois)
{
    const int n = blockIdx.x;
    const int t = threadIdx.x;   // channel index 0..191

    __shared__ int   s_iy0[14], s_iy1[14], s_ix0[14], s_ix1[14];
    __shared__ float s_ly[14],  s_vy[14],  s_lx[14],  s_vx[14];
    __shared__ float s_t[KDIM]; // 9408 floats = 36.75 KB transpose buffer

    // every thread redundantly computes ROI box + level (cheap)
    const float ry1 = rois[n * 5 + 0];
    const float rx1 = rois[n * 5 + 1];
    const float ry2 = rois[n * 5 + 2];
    const float rx2 = rois[n * 5 + 3];
    const int   bix = (int)rois[n * 5 + 4];

    const float hh = ry2 - ry1;
    const float ww = rx2 - rx1;
    int lvl = (int)rintf(4.0f + log2f(sqrtf(hh * ww)));
    lvl = min(max(lvl, 0), 3);

    const int H = 128 >> lvl;
    const int W = H;
    const float sy1 = ry1 * (float)H, sy2 = ry2 * (float)H;
    const float sx1 = rx1 * (float)W, sx2 = rx2 * (float)W;
    const float binh = fmaxf(sy2 - sy1, 1.0f) * (1.0f / 7.0f);
    const float binw = fmaxf(sx2 - sx1, 1.0f) * (1.0f / 7.0f);

    if (t < 14) {
        const float g  = (float)(t >> 1) + ((float)(t & 1) + 0.5f) * 0.5f;
        float yv = sy1 + g * binh;
        const float vy = (yv >= -1.0f && yv <= (float)H) ? 1.0f : 0.0f;
        yv = fminf(fmaxf(yv, 0.0f), (float)(H - 1));
        const int y0 = (int)floorf(yv);
        s_iy0[t] = y0;
        s_iy1[t] = min(y0 + 1, H - 1);
        s_ly[t]  = yv - (float)y0;
        s_vy[t]  = vy;
    } else if (t < 28) {
        const int u = t - 14;
        const float g  = (float)(u >> 1) + ((float)(u & 1) + 0.5f) * 0.5f;
        float xv = sx1 + g * binw;
        const float vx = (xv >= -1.0f && xv <= (float)W) ? 1.0f : 0.0f;
        xv = fminf(fmaxf(xv, 0.0f), (float)(W - 1));
        const int x0 = (int)floorf(xv);
        s_ix0[u] = x0;
        s_ix1[u] = min(x0 + 1, W - 1);
        s_lx[u]  = xv - (float)x0;
        s_vx[u]  = vx;
    }
    __syncthreads();

    const float* fsel = (lvl == 0) ? f0 : (lvl == 1) ? f1 : (lvl == 2) ? f2 : f3;
    const float* plane = fsel + ((size_t)bix * CCH + t) * (size_t)(H * W);

    for (int i = 0; i < 7; i++) {
        float a[7] = {0.f, 0.f, 0.f, 0.f, 0.f, 0.f, 0.f};
        #pragma unroll
        for (int s1 = 0; s1 < 2; s1++) {
            const int iy = i * 2 + s1;
            const float* r0 = plane + s_iy0[iy] * W;
            const float* r1 = plane + s_iy1[iy] * W;
            const float ly  = s_ly[iy];
            const float vy  = s_vy[iy];
            const float hy1 = ly * vy;
            const float hy0 = (1.0f - ly) * vy;
            #pragma unroll
            for (int ix = 0; ix < 14; ix++) {
                const float lx = s_lx[ix];
                const float vx = s_vx[ix];
                const int x0  = s_ix0[ix];
                const int x1i = s_ix1[ix];
                const float t0 = __ldg(r0 + x0);
                const float t1 = __ldg(r0 + x1i);
                const float b0 = __ldg(r1 + x0);
                const float b1 = __ldg(r1 + x1i);
                const float top = t0 + lx * (t1 - t0);
                const float bot = b0 + lx * (b1 - b0);
                a[ix >> 1] += (hy0 * top + hy1 * bot) * vx;
            }
        }
        #pragma unroll
        for (int j = 0; j < 7; j++)
            s_t[t * 49 + i * 7 + j] = a[j] * 0.25f;
    }
    __syncthreads();

    // coalesced write-out
    float* dst = g_pooled + (size_t)n * KDIM;
    #pragma unroll 7
    for (int r = 0; r < 49; r++)
        dst[r * 192 + t] = s_t[r * 192 + t];
}

// ---------------------------------------------------------------------------
// Kernel 2/4: NT SGEMM (C = A[M,K] * B[N,K]^T), split-K into g_part.
// BM=BN=64, BK=16, 256 threads, 4x4 per thread via packed f32x2 FMA.
// mode 0: A = g_pooled (K=9408); mode 1: A = g_x1 (K=768).
// ---------------------------------------------------------------------------
__global__ __launch_bounds__(256) void sgemm_nt_split(
    const float* __restrict__ Bw, int mode, int K, int klen)
{
    const float* A = (mode == 0) ? g_pooled : g_x1;
    const int M = NROIS, N = DDIM;

    __shared__ float As[16][64];
    __shared__ float Bs[16][64];

    const int tid = threadIdx.x;
    const int tx = tid & 15;        // n direction
    const int ty = tid >> 4;        // m direction
    const int m0 = blockIdx.x * 64;
    const int n0 = blockIdx.y * 64;
    const int kbeg = blockIdx.z * klen;

    const int lrow = tid >> 2;          // 0..63
    const int lk4  = (tid & 3) * 4;     // 0,4,8,12

    const float* aptr = A  + (size_t)(m0 + lrow) * K + kbeg + lk4;
    const float* bptr = Bw + (size_t)(n0 + lrow) * K + kbeg + lk4;
    const bool aval = (m0 + lrow) < M;

    unsigned long long acc[4][2];
    #pragma unroll
    for (int i = 0; i < 4; i++) { acc[i][0] = 0ull; acc[i][1] = 0ull; }

    for (int kk = 0; kk < klen; kk += 16) {
        const float4 av4 = aval ? *(const float4*)aptr : make_float4(0.f, 0.f, 0.f, 0.f);
        const float4 bv4 = *(const float4*)bptr;
        aptr += 16; bptr += 16;

        As[lk4 + 0][lrow] = av4.x;
        As[lk4 + 1][lrow] = av4.y;
        As[lk4 + 2][lrow] = av4.z;
        As[lk4 + 3][lrow] = av4.w;
        Bs[lk4 + 0][lrow] = bv4.x;
        Bs[lk4 + 1][lrow] = bv4.y;
        Bs[lk4 + 2][lrow] = bv4.z;
        Bs[lk4 + 3][lrow] = bv4.w;
        __syncthreads();

        #pragma unroll
        for (int k = 0; k < 16; k++) {
            const float4 a = *(const float4*)&As[k][ty * 4];
            const ulonglong2 b = *(const ulonglong2*)&Bs[k][tx * 4];
            const unsigned long long a0 = pack2(a.x, a.x);
            const unsigned long long a1 = pack2(a.y, a.y);
            const unsigned long long a2 = pack2(a.z, a.z);
            const unsigned long long a3 = pack2(a.w, a.w);
            fma2(acc[0][0], a0, b.x); fma2(acc[0][1], a0, b.y);
            fma2(acc[1][0], a1, b.x); fma2(acc[1][1], a1, b.y);
            fma2(acc[2][0], a2, b.x); fma2(acc[2][1], a2, b.y);
            fma2(acc[3][0], a3, b.x); fma2(acc[3][1], a3, b.y);
        }
        __syncthreads();
    }

    float* outp = g_part + (size_t)blockIdx.z * M * N;
    #pragma unroll
    for (int i = 0; i < 4; i++) {
        const int gm = m0 + ty * 4 + i;
        if (gm < M) {
            const float2 c0 = unpack2(acc[i][0]);
            const float2 c1 = unpack2(acc[i][1]);
            float* row = outp + (size_t)gm * N + n0 + tx * 4;
            row[0] = c0.x; row[1] = c0.y; row[2] = c1.x; row[3] = c1.y;
        }
    }
}

// ---------------------------------------------------------------------------
// Kernel 3/5: reduce split-K partials + bias + relu
// mode 0 -> g_x1, mode 1 -> g_x2
// ---------------------------------------------------------------------------
__global__ __launch_bounds__(256) void combine_bias_relu(
    const float* __restrict__ bias, int mode)
{
    const int idx = blockIdx.x * 256 + threadIdx.x;
    if (idx >= MN) return;
    float s = bias[idx % DDIM];
    s += g_part[idx];
    s += g_part[MN + idx];
    s += g_part[2 * MN + idx];
    s += g_part[3 * MN + idx];
    float* out = (mode == 0) ? g_x1 : g_x2;
    out[idx] = fmaxf(s, 0.0f);
}

// ---------------------------------------------------------------------------
// Kernel 6: head projections. 1 block / ROI, 4 warps over 14 outputs.
// Output layout: [0,8000) bbox (n*8+o) | [8000,10000) logits (n*2+h)
//                | [10000,14000) regress (n*4 + h*2 + {reg,unc})
// ---------------------------------------------------------------------------
__global__ __launch_bounds__(128) void heads_kernel(
    const float* __restrict__ wb, const float* __restrict__ bb,
    const float* __restrict__ wc, const float* __restrict__ bc,
    const float* __restrict__ wr, const float* __restrict__ br,
    const float* __restrict__ wu, const float* __restrict__ bu,
    float* __restrict__ out)
{
    const int n = blockIdx.x;
    const int tid = threadIdx.x;
    const int lane = tid & 31;
    const int warp = tid >> 5;

    __shared__ float sx[DDIM];
    #pragma unroll
    for (int r = 0; r < DDIM / 128; r++)
        sx[r * 128 + tid] = g_x2[(size_t)n * DDIM + r * 128 + tid];
    __syncthreads();

    for (int o = warp; o < 14; o += 4) {
        const float* wt;
        float bias;
        if (o < 8)       { wt = wb + o * DDIM;        bias = bb[o]; }
        else if (o < 10) { wt = wc + (o - 8) * DDIM;  bias = bc[o - 8]; }
        else if (o < 12) { wt = wr + (o - 10) * DDIM; bias = br[o - 10]; }
        else             { wt = wu + (o - 12) * DDIM; bias = bu[o - 12]; }

        float s = 0.0f;
        #pragma unroll
        for (int k = lane; k < DDIM; k += 32)
            s += sx[k] * __ldg(wt + k);
        #pragma unroll
        for (int off = 16; off; off >>= 1)
            s += __shfl_down_sync(0xffffffffu, s, off);

        if (lane == 0) {
            const float v = s + bias;
            if (o < 8)       out[n * 8 + o] = v;
            else if (o < 10) out[8000  + n * 2 + (o - 8)] = v;
            else if (o < 12) out[10000 + n * 4 + (o - 10) * 2 + 0] = v;
            else             out[10000 + n * 4 + (o - 12) * 2 + 1] = v;
        }
    }
}

// ---------------------------------------------------------------------------
extern "C" void kernel_launch(void* const* d_in, const int* in_sizes, int n_in,
                              void* d_out, int out_size)
{
    const float* f0   = (const float*)d_in[0];
    const float* f1   = (const float*)d_in[1];
    const float* f2   = (const float*)d_in[2];
    const float* f3   = (const float*)d_in[3];
    const float* rois = (const float*)d_in[4];
    const float* w1   = (const float*)d_in[5];
    const float* b1   = (const float*)d_in[6];
    const float* w2   = (const float*)d_in[7];
    const float* b2   = (const float*)d_in[8];
    const float* wb   = (const float*)d_in[9];
    const float* bb   = (const float*)d_in[10];
    const float* wc   = (const float*)d_in[11];
    const float* bc   = (const float*)d_in[12];
    const float* wr   = (const float*)d_in[13];
    const float* br   = (const float*)d_in[14];
    const float* wu   = (const float*)d_in[15];
    const float* bu   = (const float*)d_in[16];
    float* out = (float*)d_out;

    roi_align_kernel<<<NROIS, 192>>>(f0, f1, f2, f3, rois);

    // FC1: [1000,9408] x [768,9408]^T, split-K=4 (klen 2352)
    sgemm_nt_split<<<dim3(16, 12, KSPLIT), 256>>>(w1, 0, KDIM, KDIM / KSPLIT);
    combine_bias_relu<<<(MN + 255) / 256, 256>>>(b1, 0);

    // FC2: [1000,768] x [768,768]^T, split-K=4 (klen 192)
    sgemm_nt_split<<<dim3(16, 12, KSPLIT), 256>>>(w2, 1, DDIM, DDIM / KSPLIT);
    combine_bias_relu<<<(MN + 255) / 256, 256>>>(b2, 1);

    heads_kernel<<<NROIS, 128>>>(wb, bb, wc, bc, wr, br, wu, bu, out);
}

// round 5
// speedup vs baseline: 3.1403x; 3.1403x over previous
#include <cuda_runtime.h>
#include <cuda_fp16.h>
#include <cstdint>

#define NROIS 1000
#define CCH   192
#define KDIM  9408
#define DDIM  768
#define MPAD  1024
#define MN    (MPAD * DDIM)

// ---------------- scratch (device globals; allocation forbidden) -----------
// NOTE: these symbols are ONLY referenced from device code (host code cannot
// take the address of a __device__ variable — that was the R3/R4 bug).
__device__ __half g_A[MPAD * KDIM];         // pooled, fp16
__device__ __half g_B1h[DDIM * KDIM];       // w1 hi
__device__ __half g_B1l[DDIM * KDIM];       // w1 lo (residual)
__device__ __half g_B2h[DDIM * DDIM];
__device__ __half g_B2l[DDIM * DDIM];
__device__ __half g_x1h[MN];
__device__ __half g_x1l[MN];
__device__ float  g_x2[MN];
__device__ float  g_part[3 * MN];           // split-K partials

__device__ __forceinline__ uint32_t smem_u32(const void* p) {
    uint32_t a;
    asm("{ .reg .u64 t; cvta.to.shared.u64 t, %1; cvt.u32.u64 %0, t; }"
        : "=r"(a) : "l"(p));
    return a;
}
__device__ __forceinline__ uint32_t pkh(__half a, __half b) {
    return (uint32_t)__half_as_ushort(a) | ((uint32_t)__half_as_ushort(b) << 16);
}
__device__ __forceinline__ void ldm4(uint32_t* r, uint32_t addr) {
    asm volatile("ldmatrix.sync.aligned.m8n8.x4.shared.b16 {%0,%1,%2,%3}, [%4];"
        : "=r"(r[0]), "=r"(r[1]), "=r"(r[2]), "=r"(r[3]) : "r"(addr));
}
__device__ __forceinline__ void mma16816(float* c, const uint32_t* a,
                                         uint32_t b0, uint32_t b1) {
    asm volatile(
        "mma.sync.aligned.m16n8k16.row.col.f32.f16.f16.f32 "
        "{%0,%1,%2,%3}, {%4,%5,%6,%7}, {%8,%9}, {%0,%1,%2,%3};"
        : "+f"(c[0]), "+f"(c[1]), "+f"(c[2]), "+f"(c[3])
        : "r"(a[0]), "r"(a[1]), "r"(a[2]), "r"(a[3]), "r"(b0), "r"(b1));
}
__device__ __forceinline__ void cpa16(uint32_t saddr, const void* g) {
    asm volatile("cp.async.cg.shared.global [%0], [%1], 16;"
                 :: "r"(saddr), "l"(g));
}

// ---------------------------------------------------------------------------
// Kernel 0: split fp32 weights -> fp16 hi + lo. sel 0 -> w1, sel 1 -> w2.
// ---------------------------------------------------------------------------
__global__ __launch_bounds__(256) void split_w(const float4* __restrict__ src,
                                               int sel, int n4)
{
    int i = blockIdx.x * 256 + threadIdx.x;
    if (i >= n4) return;
    const float4 v = src[i];
    const __half hx = __float2half_rn(v.x);
    const __half hy = __float2half_rn(v.y);
    const __half hz = __float2half_rn(v.z);
    const __half hw = __float2half_rn(v.w);
    uint2 H, L;
    H.x = pkh(hx, hy);
    H.y = pkh(hz, hw);
    L.x = pkh(__float2half_rn(v.x - __half2float(hx)),
              __float2half_rn(v.y - __half2float(hy)));
    L.y = pkh(__float2half_rn(v.z - __half2float(hz)),
              __float2half_rn(v.w - __half2float(hw)));
    uint2* hi = (uint2*)(sel == 0 ? g_B1h : g_B2h);
    uint2* lo = (uint2*)(sel == 0 ? g_B1l : g_B2l);
    hi[i] = H;
    lo[i] = L;
}

// ---------------------------------------------------------------------------
// Kernel 1: pyramid RoIAlign. 1 block/ROI, 192 threads (6 warps).
// Warp lanes = spatial samples of a single channel plane.
// Output: g_A[n][c*49 + i*7 + j] fp16.
// ---------------------------------------------------------------------------
__global__ __launch_bounds__(192) void roi_align_kernel(
    const float* __restrict__ f0, const float* __restrict__ f1,
    const float* __restrict__ f2, const float* __restrict__ f3,
    const float* __restrict__ rois)
{
    const int n = blockIdx.x;
    const int t = threadIdx.x;
    const int lane = t & 31;
    const int wid = t >> 5;

    __shared__ float s_w00[196], s_w01[196], s_w10[196], s_w11[196];
    __shared__ int   s_o00[196], s_o01[196], s_o10[196], s_o11[196];
    __shared__ __half s_h[KDIM];

    const float ry1 = rois[n * 5 + 0];
    const float rx1 = rois[n * 5 + 1];
    const float ry2 = rois[n * 5 + 2];
    const float rx2 = rois[n * 5 + 3];
    const int   bix = (int)rois[n * 5 + 4];

    int lvl = (int)rintf(4.0f + log2f(sqrtf((ry2 - ry1) * (rx2 - rx1))));
    lvl = min(max(lvl, 0), 3);
    const int H = 128 >> lvl;
    const int W = H;
    const float sy1 = ry1 * (float)H, sx1 = rx1 * (float)W;
    const float binh = fmaxf((ry2 - ry1) * (float)H, 1.0f) * (1.0f / 7.0f);
    const float binw = fmaxf((rx2 - rx1) * (float)W, 1.0f) * (1.0f / 7.0f);

    for (int s = t; s < 196; s += 192) {
        const int sy = s / 14, sx = s - sy * 14;
        const float gy = (float)(sy >> 1) + ((float)(sy & 1) + 0.5f) * 0.5f;
        const float gx = (float)(sx >> 1) + ((float)(sx & 1) + 0.5f) * 0.5f;
        float y = sy1 + gy * binh;
        float x = sx1 + gx * binw;
        const bool vld = (y >= -1.0f) && (y <= (float)H) && (x >= -1.0f) && (x <= (float)W);
        y = fminf(fmaxf(y, 0.0f), (float)(H - 1));
        x = fminf(fmaxf(x, 0.0f), (float)(W - 1));
        const int y0 = (int)floorf(y);
        const int x0 = (int)floorf(x);
        const int y1i = min(y0 + 1, H - 1);
        const int x1i = min(x0 + 1, W - 1);
        const float ly = y - (float)y0, lx = x - (float)x0;
        const float vf = vld ? 0.25f : 0.0f;   // fold 2x2-bin mean
        s_w00[s] = (1.0f - ly) * (1.0f - lx) * vf;
        s_w01[s] = (1.0f - ly) * lx * vf;
        s_w10[s] = ly * (1.0f - lx) * vf;
        s_w11[s] = ly * lx * vf;
        s_o00[s] = y0 * W + x0;
        s_o01[s] = y0 * W + x1i;
        s_o10[s] = y1i * W + x0;
        s_o11[s] = y1i * W + x1i;
    }
    __syncthreads();

    const float* fsel = (lvl == 0) ? f0 : (lvl == 1) ? f1 : (lvl == 2) ? f2 : f3;
    const float* base = fsel + (size_t)bix * CCH * (size_t)(H * W);
    const int HW = H * W;

    const int in28 = (lane < 28);
    const int srow_off = (lane >= 14 && lane < 28) ? 1 : 0;
    const int sxi = (lane < 14) ? lane : lane - 14;

    #pragma unroll
    for (int i = 0; i < 7; i++) {
        const int s = (2 * i + srow_off) * 14 + sxi;  // reads guarded by in28
        float w00 = 0.f, w01 = 0.f, w10 = 0.f, w11 = 0.f;
        int o00 = 0, o01 = 0, o10 = 0, o11 = 0;
        if (in28) {
            w00 = s_w00[s]; w01 = s_w01[s]; w10 = s_w10[s]; w11 = s_w11[s];
            o00 = s_o00[s]; o01 = s_o01[s]; o10 = s_o10[s]; o11 = s_o11[s];
        }
        const float* pl = base + (size_t)(wid * 32) * HW;
        for (int ci = 0; ci < 32; ci++, pl += HW) {
            float v = w00 * __ldg(pl + o00) + w01 * __ldg(pl + o01)
                    + w10 * __ldg(pl + o10) + w11 * __ldg(pl + o11);
            v += __shfl_xor_sync(0xffffffffu, v, 1);
            v += __shfl_down_sync(0xffffffffu, v, 14);
            if (lane < 14 && !(lane & 1)) {
                const int c = wid * 32 + ci;
                s_h[c * 49 + i * 7 + (lane >> 1)] = __float2half_rn(v);
            }
        }
    }
    __syncthreads();

    const uint32_t* sh = (const uint32_t*)s_h;
    uint32_t* dh = (uint32_t*)(g_A + (size_t)n * KDIM);
    for (int idx = t; idx < KDIM / 2; idx += 192)
        dh[idx] = sh[idx];
}

// ---------------------------------------------------------------------------
// Kernel 2: mma.sync fp16 GEMM, BM=128, BN=64, BK=32, split-K (grid.z).
// Static shared memory ONLY (<48KB). mode 0: FC1 (A=g_A, B=g_B1h/l)
//                                    mode 1: FC2 (A=g_x1h/l, B=g_B2h/l)
// NPASS=2 (STAGES=2): D = Ah*(Bh+Bl)
// NPASS=3 (STAGES=1): D = Ah*(Bh+Bl) + Al*Bh
// Writes fp32 partials to g_part[z].
// ---------------------------------------------------------------------------
#define PITCHB 80            // 32 halves (64B) + 16B pad per row

template <int NPASS, int STAGES>
__global__ __launch_bounds__(256, 1) void gemm_fp16(int mode, int K, int chunks)
{
    constexpr int ROWS_STAGE = (NPASS == 3) ? 384 : 256;  // Ah128 [+Al128] +Bh64+Bl64
    constexpr int OFF_AL = 128 * PITCHB;                   // NPASS==3 only
    constexpr int OFF_BH = (NPASS == 3) ? 256 * PITCHB : 128 * PITCHB;
    constexpr int OFF_BL = OFF_BH + 64 * PITCHB;
    constexpr int STAGE_BYTES = ROWS_STAGE * PITCHB;

    __shared__ __align__(128) char gsm[STAGE_BYTES * STAGES];
    const uint32_t sb0 = smem_u32(gsm);

    // select operands in DEVICE code (device globals are not host-addressable)
    const __half* __restrict__ Ah = (mode == 0) ? g_A   : g_x1h;
    const __half* __restrict__ Al = (mode == 0) ? g_A   : g_x1l;   // unused if NPASS==2
    const __half* __restrict__ Bh = (mode == 0) ? g_B1h : g_B2h;
    const __half* __restrict__ Bl = (mode == 0) ? g_B1l : g_B2l;

    const int tid = threadIdx.x;
    const int lane = tid & 31;
    const int wid = tid >> 5;
    const int wm = wid & 3;            // 4 m-tiles of 32
    const int wn = wid >> 2;           // 2 n-tiles of 32
    const int m0 = blockIdx.x * 128;
    const int n0 = blockIdx.y * 64;
    const int kbeg = blockIdx.z * chunks * 32;

    const int lrow = tid >> 2;          // 0..63
    const int lc = tid & 3;             // 16B chunk in 64B row

    auto load_stage = [&](int st, int kc) {
        const int kk = kbeg + kc * 32;
        const uint32_t sb = sb0 + st * STAGE_BYTES;
        const uint32_t so = lrow * PITCHB + lc * 16;
        const size_t gOff = (size_t)lc * 8 + kk;
        cpa16(sb + so, Ah + (size_t)(m0 + lrow) * K + gOff);
        cpa16(sb + so + 64 * PITCHB, Ah + (size_t)(m0 + lrow + 64) * K + gOff);
        if (NPASS == 3) {
            cpa16(sb + OFF_AL + so, Al + (size_t)(m0 + lrow) * K + gOff);
            cpa16(sb + OFF_AL + so + 64 * PITCHB,
                  Al + (size_t)(m0 + lrow + 64) * K + gOff);
        }
        cpa16(sb + OFF_BH + so, Bh + (size_t)(n0 + lrow) * K + gOff);
        cpa16(sb + OFF_BL + so, Bl + (size_t)(n0 + lrow) * K + gOff);
        asm volatile("cp.async.commit_group;");
    };

    float acc[2][4][4];
    #pragma unroll
    for (int m = 0; m < 2; m++)
        #pragma unroll
        for (int nt = 0; nt < 4; nt++)
            #pragma unroll
            for (int e = 0; e < 4; e++) acc[m][nt][e] = 0.0f;

    load_stage(0, 0);

    const uint32_t lr16 = lane & 15;
    const uint32_t lch = (lane >> 4) * 16;

    for (int c = 0; c < chunks; c++) {
        const int cur = (STAGES == 2) ? (c & 1) : 0;
        if (STAGES == 2 && c + 1 < chunks) {
            load_stage(1 - cur, c + 1);
            asm volatile("cp.async.wait_group 1;");
        } else {
            asm volatile("cp.async.wait_group 0;");
        }
        __syncthreads();

        const uint32_t sb = sb0 + cur * STAGE_BYTES;
        #pragma unroll
        for (int ks = 0; ks < 2; ks++) {
            const uint32_t colb = ks * 32 + lch;
            uint32_t ah[2][4], al[2][4], bh[2][4], bl[2][4];
            #pragma unroll
            for (int tm = 0; tm < 2; tm++) {
                const uint32_t r = wm * 32 + tm * 16 + lr16;
                ldm4(ah[tm], sb + r * PITCHB + colb);
                if (NPASS == 3)
                    ldm4(al[tm], sb + OFF_AL + r * PITCHB + colb);
            }
            #pragma unroll
            for (int g = 0; g < 2; g++) {
                const uint32_t r = wn * 32 + g * 16 + lr16;
                ldm4(bh[g], sb + OFF_BH + r * PITCHB + colb);
                ldm4(bl[g], sb + OFF_BL + r * PITCHB + colb);
            }
            #pragma unroll
            for (int tm = 0; tm < 2; tm++) {
                #pragma unroll
                for (int nt = 0; nt < 4; nt++) {
                    const int g = nt >> 1, s = nt & 1;
                    mma16816(acc[tm][nt], ah[tm], bh[g][s], bh[g][s + 2]);
                    mma16816(acc[tm][nt], ah[tm], bl[g][s], bl[g][s + 2]);
                    if (NPASS == 3)
                        mma16816(acc[tm][nt], al[tm], bh[g][s], bh[g][s + 2]);
                }
            }
        }
        __syncthreads();
        if (STAGES == 1 && c + 1 < chunks)
            load_stage(0, c + 1);
    }

    float* P = g_part + (size_t)blockIdx.z * MN;
    #pragma unroll
    for (int tm = 0; tm < 2; tm++) {
        const int gr = m0 + wm * 32 + tm * 16 + (lane >> 2);
        #pragma unroll
        for (int nt = 0; nt < 4; nt++) {
            const int gc = n0 + wn * 32 + nt * 8 + (lane & 3) * 2;
            *(float2*)&P[(size_t)gr * DDIM + gc] =
                make_float2(acc[tm][nt][0], acc[tm][nt][1]);
            *(float2*)&P[(size_t)(gr + 8) * DDIM + gc] =
                make_float2(acc[tm][nt][2], acc[tm][nt][3]);
        }
    }
}

// ---------------------------------------------------------------------------
// Kernel 3: combine 3 split-K partials + bias + relu.
// mode 0 -> g_x1h/g_x1l (fp16 split), mode 1 -> g_x2 (fp32)
// ---------------------------------------------------------------------------
__global__ __launch_bounds__(256) void combine_bias_relu(
    const float* __restrict__ bias, int mode)
{
    const int i2 = blockIdx.x * 256 + threadIdx.x;
    if (i2 >= MN / 2) return;
    const int col = (i2 * 2) % DDIM;
    const float2 p0 = ((const float2*)g_part)[i2];
    const float2 p1 = ((const float2*)(g_part + MN))[i2];
    const float2 p2 = ((const float2*)(g_part + 2 * MN))[i2];
    const float v0 = fmaxf(p0.x + p1.x + p2.x + bias[col], 0.0f);
    const float v1 = fmaxf(p0.y + p1.y + p2.y + bias[col + 1], 0.0f);
    if (mode == 0) {
        const __half h0 = __float2half_rn(v0);
        const __half h1 = __float2half_rn(v1);
        ((uint32_t*)g_x1h)[i2] = pkh(h0, h1);
        ((uint32_t*)g_x1l)[i2] =
            pkh(__float2half_rn(v0 - __half2float(h0)),
                __float2half_rn(v1 - __half2float(h1)));
    } else {
        ((float2*)g_x2)[i2] = make_float2(v0, v1);
    }
}

// ---------------------------------------------------------------------------
// Kernel 4: head projections (14 outputs per ROI)
// ---------------------------------------------------------------------------
__global__ __launch_bounds__(128) void heads_kernel(
    const float* __restrict__ wb, const float* __restrict__ bb,
    const float* __restrict__ wc, const float* __restrict__ bc,
    const float* __restrict__ wr, const float* __restrict__ br,
    const float* __restrict__ wu, const float* __restrict__ bu,
    float* __restrict__ out)
{
    const int n = blockIdx.x;
    const int tid = threadIdx.x;
    const int lane = tid & 31;
    const int warp = tid >> 5;

    __shared__ float sx[DDIM];
    #pragma unroll
    for (int r = 0; r < DDIM / 128; r++)
        sx[r * 128 + tid] = g_x2[(size_t)n * DDIM + r * 128 + tid];
    __syncthreads();

    for (int o = warp; o < 14; o += 4) {
        const float* wt;
        float bias;
        if (o < 8)       { wt = wb + o * DDIM;        bias = bb[o]; }
        else if (o < 10) { wt = wc + (o - 8) * DDIM;  bias = bc[o - 8]; }
        else if (o < 12) { wt = wr + (o - 10) * DDIM; bias = br[o - 10]; }
        else             { wt = wu + (o - 12) * DDIM; bias = bu[o - 12]; }

        float s = 0.0f;
        #pragma unroll
        for (int k = lane; k < DDIM; k += 32)
            s += sx[k] * __ldg(wt + k);
        #pragma unroll
        for (int off = 16; off; off >>= 1)
            s += __shfl_down_sync(0xffffffffu, s, off);

        if (lane == 0) {
            const float v = s + bias;
            if (o < 8)       out[n * 8 + o] = v;
            else if (o < 10) out[8000  + n * 2 + (o - 8)] = v;
            else if (o < 12) out[10000 + n * 4 + (o - 10) * 2 + 0] = v;
            else             out[10000 + n * 4 + (o - 12) * 2 + 1] = v;
        }
    }
}

// ---------------------------------------------------------------------------
extern "C" void kernel_launch(void* const* d_in, const int* in_sizes, int n_in,
                              void* d_out, int out_size)
{
    const float* f0   = (const float*)d_in[0];
    const float* f1   = (const float*)d_in[1];
    const float* f2   = (const float*)d_in[2];
    const float* f3   = (const float*)d_in[3];
    const float* rois = (const float*)d_in[4];
    const float* w1   = (const float*)d_in[5];
    const float* b1   = (const float*)d_in[6];
    const float* w2   = (const float*)d_in[7];
    const float* b2   = (const float*)d_in[8];
    const float* wb   = (const float*)d_in[9];
    const float* bb   = (const float*)d_in[10];
    const float* wc   = (const float*)d_in[11];
    const float* bc   = (const float*)d_in[12];
    const float* wr   = (const float*)d_in[13];
    const float* br   = (const float*)d_in[14];
    const float* wu   = (const float*)d_in[15];
    const float* bu   = (const float*)d_in[16];
    float* out = (float*)d_out;

    // weight splits (fp16 hi/lo)
    split_w<<<(DDIM * KDIM / 4 + 255) / 256, 256>>>((const float4*)w1, 0, DDIM * KDIM / 4);
    split_w<<<(DDIM * DDIM / 4 + 255) / 256, 256>>>((const float4*)w2, 1, DDIM * DDIM / 4);

    // RoIAlign -> fp16 A
    roi_align_kernel<<<NROIS, 192>>>(f0, f1, f2, f3, rois);

    // FC1: [1024,9408] @ [768,9408]^T, 2-pass, split-K=3 (98 chunks each)
    gemm_fp16<2, 2><<<dim3(MPAD / 128, DDIM / 64, 3), 256>>>(0, KDIM, KDIM / 96);
    combine_bias_relu<<<(MN / 2 + 255) / 256, 256>>>(b1, 0);

    // FC2: [1024,768] @ [768,768]^T, 3-pass, split-K=3 (8 chunks each)
    gemm_fp16<3, 1><<<dim3(MPAD / 128, DDIM / 64, 3), 256>>>(1, DDIM, DDIM / 96);
    combine_bias_relu<<<(MN / 2 + 255) / 256, 256>>>(b2, 1);

    heads_kernel<<<NROIS, 128>>>(wb, bb, wc, bc, wr, br, wu, bu, out);
}

// round 6
// speedup vs baseline: 5.7421x; 1.8285x over previous
#include <cuda_runtime.h>
#include <cuda_fp16.h>
#include <cstdint>

#define NROIS 1000
#define CCH   192
#define KDIM  9408
#define DDIM  768
#define MPAD  1024
#define MN    (MPAD * DDIM)
#define KSPLIT1 6
#define KSPLIT2 3

// ---------------- scratch (device globals; only referenced in device code) --
__device__ __half g_A[MPAD * KDIM];         // pooled, fp16
__device__ __half g_B1h[DDIM * KDIM];       // w1 fp16 (single-pass)
__device__ __half g_B2h[DDIM * DDIM];       // w2 hi
__device__ __half g_B2l[DDIM * DDIM];       // w2 lo residual
__device__ __half g_x1h[MN];
__device__ __half g_x1l[MN];
__device__ float  g_x2[MN];
__device__ float  g_part[KSPLIT1 * MN];     // split-K partials

__device__ __forceinline__ uint32_t smem_u32(const void* p) {
    uint32_t a;
    asm("{ .reg .u64 t; cvta.to.shared.u64 t, %1; cvt.u32.u64 %0, t; }"
        : "=r"(a) : "l"(p));
    return a;
}
__device__ __forceinline__ uint32_t pkh(__half a, __half b) {
    return (uint32_t)__half_as_ushort(a) | ((uint32_t)__half_as_ushort(b) << 16);
}
__device__ __forceinline__ void ldm4(uint32_t* r, uint32_t addr) {
    asm volatile("ldmatrix.sync.aligned.m8n8.x4.shared.b16 {%0,%1,%2,%3}, [%4];"
        : "=r"(r[0]), "=r"(r[1]), "=r"(r[2]), "=r"(r[3]) : "r"(addr));
}
__device__ __forceinline__ void mma16816(float* c, const uint32_t* a,
                                         uint32_t b0, uint32_t b1) {
    asm volatile(
        "mma.sync.aligned.m16n8k16.row.col.f32.f16.f16.f32 "
        "{%0,%1,%2,%3}, {%4,%5,%6,%7}, {%8,%9}, {%0,%1,%2,%3};"
        : "+f"(c[0]), "+f"(c[1]), "+f"(c[2]), "+f"(c[3])
        : "r"(a[0]), "r"(a[1]), "r"(a[2]), "r"(a[3]), "r"(b0), "r"(b1));
}
__device__ __forceinline__ void cpa16(uint32_t saddr, const void* g) {
    asm volatile("cp.async.cg.shared.global [%0], [%1], 16;"
                 :: "r"(saddr), "l"(g));
}

// ---------------------------------------------------------------------------
// Kernel 0: weight conversion. sel 0 -> w1 fp16 only; sel 1 -> w2 hi+lo.
// ---------------------------------------------------------------------------
__global__ __launch_bounds__(256) void split_w(const float4* __restrict__ src,
                                               int sel, int n4)
{
    int i = blockIdx.x * 256 + threadIdx.x;
    if (i >= n4) return;
    const float4 v = src[i];
    const __half hx = __float2half_rn(v.x);
    const __half hy = __float2half_rn(v.y);
    const __half hz = __float2half_rn(v.z);
    const __half hw = __float2half_rn(v.w);
    uint2 H;
    H.x = pkh(hx, hy);
    H.y = pkh(hz, hw);
    if (sel == 0) {
        ((uint2*)g_B1h)[i] = H;
    } else {
        uint2 L;
        L.x = pkh(__float2half_rn(v.x - __half2float(hx)),
                  __float2half_rn(v.y - __half2float(hy)));
        L.y = pkh(__float2half_rn(v.z - __half2float(hz)),
                  __float2half_rn(v.w - __half2float(hw)));
        ((uint2*)g_B2h)[i] = H;
        ((uint2*)g_B2l)[i] = L;
    }
}

// ---------------------------------------------------------------------------
// Kernel 1: pyramid RoIAlign. 1 block/ROI, 192 threads (6 warps).
// Warp lanes = spatial samples; 4 channels per inner iteration (MLP=16).
// Output: g_A[n][c*49 + i*7 + j] fp16.
// ---------------------------------------------------------------------------
__global__ __launch_bounds__(192) void roi_align_kernel(
    const float* __restrict__ f0, const float* __restrict__ f1,
    const float* __restrict__ f2, const float* __restrict__ f3,
    const float* __restrict__ rois)
{
    const int n = blockIdx.x;
    const int t = threadIdx.x;
    const int lane = t & 31;
    const int wid = t >> 5;

    __shared__ float s_w00[196], s_w01[196], s_w10[196], s_w11[196];
    __shared__ int   s_o00[196], s_o01[196], s_o10[196], s_o11[196];
    __shared__ __half s_h[KDIM];

    const float ry1 = rois[n * 5 + 0];
    const float rx1 = rois[n * 5 + 1];
    const float ry2 = rois[n * 5 + 2];
    const float rx2 = rois[n * 5 + 3];
    const int   bix = (int)rois[n * 5 + 4];

    int lvl = (int)rintf(4.0f + log2f(sqrtf((ry2 - ry1) * (rx2 - rx1))));
    lvl = min(max(lvl, 0), 3);
    const int H = 128 >> lvl;
    const int W = H;
    const float sy1 = ry1 * (float)H, sx1 = rx1 * (float)W;
    const float binh = fmaxf((ry2 - ry1) * (float)H, 1.0f) * (1.0f / 7.0f);
    const float binw = fmaxf((rx2 - rx1) * (float)W, 1.0f) * (1.0f / 7.0f);

    for (int s = t; s < 196; s += 192) {
        const int sy = s / 14, sx = s - sy * 14;
        const float gy = (float)(sy >> 1) + ((float)(sy & 1) + 0.5f) * 0.5f;
        const float gx = (float)(sx >> 1) + ((float)(sx & 1) + 0.5f) * 0.5f;
        float y = sy1 + gy * binh;
        float x = sx1 + gx * binw;
        const bool vld = (y >= -1.0f) && (y <= (float)H) && (x >= -1.0f) && (x <= (float)W);
        y = fminf(fmaxf(y, 0.0f), (float)(H - 1));
        x = fminf(fmaxf(x, 0.0f), (float)(W - 1));
        const int y0 = (int)floorf(y);
        const int x0 = (int)floorf(x);
        const int y1i = min(y0 + 1, H - 1);
        const int x1i = min(x0 + 1, W - 1);
        const float ly = y - (float)y0, lx = x - (float)x0;
        const float vf = vld ? 0.25f : 0.0f;   // fold 2x2-bin mean
        s_w00[s] = (1.0f - ly) * (1.0f - lx) * vf;
        s_w01[s] = (1.0f - ly) * lx * vf;
        s_w10[s] = ly * (1.0f - lx) * vf;
        s_w11[s] = ly * lx * vf;
        s_o00[s] = y0 * W + x0;
        s_o01[s] = y0 * W + x1i;
        s_o10[s] = y1i * W + x0;
        s_o11[s] = y1i * W + x1i;
    }
    __syncthreads();

    const float* fsel = (lvl == 0) ? f0 : (lvl == 1) ? f1 : (lvl == 2) ? f2 : f3;
    const float* base = fsel + (size_t)bix * CCH * (size_t)(H * W);
    const int HW = H * W;

    const int in28 = (lane < 28);
    const int srow_off = (lane >= 14 && lane < 28) ? 1 : 0;
    const int sxi = (lane < 14) ? lane : lane - 14;

    #pragma unroll
    for (int i = 0; i < 7; i++) {
        const int s = (2 * i + srow_off) * 14 + sxi;  // reads guarded by in28
        float w00 = 0.f, w01 = 0.f, w10 = 0.f, w11 = 0.f;
        int o00 = 0, o01 = 0, o10 = 0, o11 = 0;
        if (in28) {
            w00 = s_w00[s]; w01 = s_w01[s]; w10 = s_w10[s]; w11 = s_w11[s];
            o00 = s_o00[s]; o01 = s_o01[s]; o10 = s_o10[s]; o11 = s_o11[s];
        }
        const float* pl = base + (size_t)(wid * 32) * HW;
        for (int cb = 0; cb < 32; cb += 4) {
            float v[4];
            // issue all 16 loads before any reduction (MLP=16)
            #pragma unroll
            for (int u = 0; u < 4; u++) {
                const float* p = pl + (size_t)(cb + u) * HW;
                v[u] = w00 * __ldg(p + o00) + w01 * __ldg(p + o01)
                     + w10 * __ldg(p + o10) + w11 * __ldg(p + o11);
            }
            #pragma unroll
            for (int u = 0; u < 4; u++) {
                float vv = v[u];
                vv += __shfl_xor_sync(0xffffffffu, vv, 1);
                vv += __shfl_down_sync(0xffffffffu, vv, 14);
                if (lane < 14 && !(lane & 1)) {
                    const int c = wid * 32 + cb + u;
                    s_h[c * 49 + i * 7 + (lane >> 1)] = __float2half_rn(vv);
                }
            }
        }
    }
    __syncthreads();

    const uint32_t* sh = (const uint32_t*)s_h;
    uint32_t* dh = (uint32_t*)(g_A + (size_t)n * KDIM);
    for (int idx = t; idx < KDIM / 2; idx += 192)
        dh[idx] = sh[idx];
}

// ---------------------------------------------------------------------------
// Kernel 2: FC1 GEMM, single-pass fp16. BM=128, BN=128, BK=32, split-K=6.
// D = A[1024,9408] @ B1h[768,9408]^T, fp32 partials -> g_part[z].
// smem: 2 stages x (128 A-rows + 128 B-rows) x 80B = 40960B (static).
// ---------------------------------------------------------------------------
#define PITCHB 80            // 32 halves (64B) + 16B pad per row

__global__ __launch_bounds__(256, 1) void gemm_fc1(int chunks)
{
    constexpr int OFF_B = 128 * PITCHB;
    constexpr int STAGE_BYTES = 256 * PITCHB;

    __shared__ __align__(128) char gsm[STAGE_BYTES * 2];
    const uint32_t sb0 = smem_u32(gsm);

    const __half* __restrict__ A = g_A;
    const __half* __restrict__ B = g_B1h;
    const int K = KDIM;

    const int tid = threadIdx.x;
    const int lane = tid & 31;
    const int wid = tid >> 5;
    const int wm = wid & 3;            // 4 m-tiles of 32
    const int wn = wid >> 2;           // 2 n-tiles of 64
    const int m0 = blockIdx.x * 128;
    const int n0 = blockIdx.y * 128;
    const int kbeg = blockIdx.z * chunks * 32;

    const int lrow = tid >> 2;          // 0..63
    const int lc = tid & 3;

    auto load_stage = [&](int st, int kc) {
        const int kk = kbeg + kc * 32;
        const uint32_t sb = sb0 + st * STAGE_BYTES;
        const uint32_t so = lrow * PITCHB + lc * 16;
        const size_t gOff = (size_t)lc * 8 + kk;
        cpa16(sb + so, A + (size_t)(m0 + lrow) * K + gOff);
        cpa16(sb + so + 64 * PITCHB, A + (size_t)(m0 + lrow + 64) * K + gOff);
        cpa16(sb + OFF_B + so, B + (size_t)(n0 + lrow) * K + gOff);
        cpa16(sb + OFF_B + so + 64 * PITCHB, B + (size_t)(n0 + lrow + 64) * K + gOff);
        asm volatile("cp.async.commit_group;");
    };

    float acc[2][8][4];
    #pragma unroll
    for (int m = 0; m < 2; m++)
        #pragma unroll
        for (int nt = 0; nt < 8; nt++)
            #pragma unroll
            for (int e = 0; e < 4; e++) acc[m][nt][e] = 0.0f;

    load_stage(0, 0);

    const uint32_t lr16 = lane & 15;
    const uint32_t lch = (lane >> 4) * 16;

    for (int c = 0; c < chunks; c++) {
        const int cur = c & 1;
        if (c + 1 < chunks) {
            load_stage(1 - cur, c + 1);
            asm volatile("cp.async.wait_group 1;");
        } else {
            asm volatile("cp.async.wait_group 0;");
        }
        __syncthreads();

        const uint32_t sb = sb0 + cur * STAGE_BYTES;
        #pragma unroll
        for (int ks = 0; ks < 2; ks++) {
            const uint32_t colb = ks * 32 + lch;
            uint32_t ah[2][4], bh[4][4];
            #pragma unroll
            for (int tm = 0; tm < 2; tm++) {
                const uint32_t r = wm * 32 + tm * 16 + lr16;
                ldm4(ah[tm], sb + r * PITCHB + colb);
            }
            #pragma unroll
            for (int g = 0; g < 4; g++) {
                const uint32_t r = wn * 64 + g * 16 + lr16;
                ldm4(bh[g], sb + OFF_B + r * PITCHB + colb);
            }
            #pragma unroll
            for (int tm = 0; tm < 2; tm++) {
                #pragma unroll
                for (int nt = 0; nt < 8; nt++) {
                    const int g = nt >> 1, s = nt & 1;
                    mma16816(acc[tm][nt], ah[tm], bh[g][s], bh[g][s + 2]);
                }
            }
        }
        __syncthreads();
    }

    float* P = g_part + (size_t)blockIdx.z * MN;
    #pragma unroll
    for (int tm = 0; tm < 2; tm++) {
        const int gr = m0 + wm * 32 + tm * 16 + (lane >> 2);
        #pragma unroll
        for (int nt = 0; nt < 8; nt++) {
            const int gc = n0 + wn * 64 + nt * 8 + (lane & 3) * 2;
            *(float2*)&P[(size_t)gr * DDIM + gc] =
                make_float2(acc[tm][nt][0], acc[tm][nt][1]);
            *(float2*)&P[(size_t)(gr + 8) * DDIM + gc] =
                make_float2(acc[tm][nt][2], acc[tm][nt][3]);
        }
    }
}

// ---------------------------------------------------------------------------
// Kernel 3: FC2 GEMM, 3-pass (x1 hi/lo, w2 hi/lo): D = Xh*(Bh+Bl) + Xl*Bh.
// BM=128, BN=64, BK=32, split-K=3, single stage (30720B static smem).
// ---------------------------------------------------------------------------
__global__ __launch_bounds__(256, 1) void gemm_fc2(int chunks)
{
    constexpr int OFF_AL = 128 * PITCHB;
    constexpr int OFF_BH = 256 * PITCHB;
    constexpr int OFF_BL = OFF_BH + 64 * PITCHB;
    constexpr int STAGE_BYTES = 384 * PITCHB;

    __shared__ __align__(128) char gsm[STAGE_BYTES];
    const uint32_t sb = smem_u32(gsm);

    const __half* __restrict__ Ah = g_x1h;
    const __half* __restrict__ Al = g_x1l;
    const __half* __restrict__ Bh = g_B2h;
    const __half* __restrict__ Bl = g_B2l;
    const int K = DDIM;

    const int tid = threadIdx.x;
    const int lane = tid & 31;
    const int wid = tid >> 5;
    const int wm = wid & 3;
    const int wn = wid >> 2;
    const int m0 = blockIdx.x * 128;
    const int n0 = blockIdx.y * 64;
    const int kbeg = blockIdx.z * chunks * 32;

    const int lrow = tid >> 2;
    const int lc = tid & 3;

    auto load_stage = [&](int kc) {
        const int kk = kbeg + kc * 32;
        const uint32_t so = lrow * PITCHB + lc * 16;
        const size_t gOff = (size_t)lc * 8 + kk;
        cpa16(sb + so, Ah + (size_t)(m0 + lrow) * K + gOff);
        cpa16(sb + so + 64 * PITCHB, Ah + (size_t)(m0 + lrow + 64) * K + gOff);
        cpa16(sb + OFF_AL + so, Al + (size_t)(m0 + lrow) * K + gOff);
        cpa16(sb + OFF_AL + so + 64 * PITCHB, Al + (size_t)(m0 + lrow + 64) * K + gOff);
        cpa16(sb + OFF_BH + so, Bh + (size_t)(n0 + lrow) * K + gOff);
        cpa16(sb + OFF_BL + so, Bl + (size_t)(n0 + lrow) * K + gOff);
        asm volatile("cp.async.commit_group;");
    };

    float acc[2][4][4];
    #pragma unroll
    for (int m = 0; m < 2; m++)
        #pragma unroll
        for (int nt = 0; nt < 4; nt++)
            #pragma unroll
            for (int e = 0; e < 4; e++) acc[m][nt][e] = 0.0f;

    load_stage(0);

    const uint32_t lr16 = lane & 15;
    const uint32_t lch = (lane >> 4) * 16;

    for (int c = 0; c < chunks; c++) {
        asm volatile("cp.async.wait_group 0;");
        __syncthreads();

        #pragma unroll
        for (int ks = 0; ks < 2; ks++) {
            const uint32_t colb = ks * 32 + lch;
            uint32_t ah[2][4], al[2][4], bh[2][4], bl[2][4];
            #pragma unroll
            for (int tm = 0; tm < 2; tm++) {
                const uint32_t r = wm * 32 + tm * 16 + lr16;
                ldm4(ah[tm], sb + r * PITCHB + colb);
                ldm4(al[tm], sb + OFF_AL + r * PITCHB + colb);
            }
            #pragma unroll
            for (int g = 0; g < 2; g++) {
                const uint32_t r = wn * 32 + g * 16 + lr16;
                ldm4(bh[g], sb + OFF_BH + r * PITCHB + colb);
                ldm4(bl[g], sb + OFF_BL + r * PITCHB + colb);
            }
            #pragma unroll
            for (int tm = 0; tm < 2; tm++) {
                #pragma unroll
                for (int nt = 0; nt < 4; nt++) {
                    const int g = nt >> 1, s = nt & 1;
                    mma16816(acc[tm][nt], ah[tm], bh[g][s], bh[g][s + 2]);
                    mma16816(acc[tm][nt], ah[tm], bl[g][s], bl[g][s + 2]);
                    mma16816(acc[tm][nt], al[tm], bh[g][s], bh[g][s + 2]);
                }
            }
        }
        __syncthreads();
        if (c + 1 < chunks)
            load_stage(c + 1);
    }

    float* P = g_part + (size_t)blockIdx.z * MN;
    #pragma unroll
    for (int tm = 0; tm < 2; tm++) {
        const int gr = m0 + wm * 32 + tm * 16 + (lane >> 2);
        #pragma unroll
        for (int nt = 0; nt < 4; nt++) {
            const int gc = n0 + wn * 32 + nt * 8 + (lane & 3) * 2;
            *(float2*)&P[(size_t)gr * DDIM + gc] =
                make_float2(acc[tm][nt][0], acc[tm][nt][1]);
            *(float2*)&P[(size_t)(gr + 8) * DDIM + gc] =
                make_float2(acc[tm][nt][2], acc[tm][nt][3]);
        }
    }
}

// ---------------------------------------------------------------------------
// Kernel 4: combine nparts split-K partials + bias + relu.
// mode 0 -> g_x1h/g_x1l (fp16 split), mode 1 -> g_x2 (fp32)
// ---------------------------------------------------------------------------
__global__ __launch_bounds__(256) void combine_bias_relu(
    const float* __restrict__ bias, int mode, int nparts)
{
    const int i2 = blockIdx.x * 256 + threadIdx.x;
    if (i2 >= MN / 2) return;
    const int col = (i2 * 2) % DDIM;
    float s0 = bias[col], s1 = bias[col + 1];
    for (int p = 0; p < nparts; p++) {
        const float2 pv = ((const float2*)(g_part + (size_t)p * MN))[i2];
        s0 += pv.x;
        s1 += pv.y;
    }
    const float v0 = fmaxf(s0, 0.0f);
    const float v1 = fmaxf(s1, 0.0f);
    if (mode == 0) {
        const __half h0 = __float2half_rn(v0);
        const __half h1 = __float2half_rn(v1);
        ((uint32_t*)g_x1h)[i2] = pkh(h0, h1);
        ((uint32_t*)g_x1l)[i2] =
            pkh(__float2half_rn(v0 - __half2float(h0)),
                __float2half_rn(v1 - __half2float(h1)));
    } else {
        ((float2*)g_x2)[i2] = make_float2(v0, v1);
    }
}

// ---------------------------------------------------------------------------
// Kernel 5: head projections (14 outputs per ROI)
// ---------------------------------------------------------------------------
__global__ __launch_bounds__(128) void heads_kernel(
    const float* __restrict__ wb, const float* __restrict__ bb,
    const float* __restrict__ wc, const float* __restrict__ bc,
    const float* __restrict__ wr, const float* __restrict__ br,
    const float* __restrict__ wu, const float* __restrict__ bu,
    float* __restrict__ out)
{
    const int n = blockIdx.x;
    const int tid = threadIdx.x;
    const int lane = tid & 31;
    const int warp = tid >> 5;

    __shared__ float sx[DDIM];
    #pragma unroll
    for (int r = 0; r < DDIM / 128; r++)
        sx[r * 128 + tid] = g_x2[(size_t)n * DDIM + r * 128 + tid];
    __syncthreads();

    for (int o = warp; o < 14; o += 4) {
        const float* wt;
        float bias;
        if (o < 8)       { wt = wb + o * DDIM;        bias = bb[o]; }
        else if (o < 10) { wt = wc + (o - 8) * DDIM;  bias = bc[o - 8]; }
        else if (o < 12) { wt = wr + (o - 10) * DDIM; bias = br[o - 10]; }
        else             { wt = wu + (o - 12) * DDIM; bias = bu[o - 12]; }

        float s = 0.0f;
        #pragma unroll
        for (int k = lane; k < DDIM; k += 32)
            s += sx[k] * __ldg(wt + k);
        #pragma unroll
        for (int off = 16; off; off >>= 1)
            s += __shfl_down_sync(0xffffffffu, s, off);

        if (lane == 0) {
            const float v = s + bias;
            if (o < 8)       out[n * 8 + o] = v;
            else if (o < 10) out[8000  + n * 2 + (o - 8)] = v;
            else if (o < 12) out[10000 + n * 4 + (o - 10) * 2 + 0] = v;
            else             out[10000 + n * 4 + (o - 12) * 2 + 1] = v;
        }
    }
}

// ---------------------------------------------------------------------------
extern "C" void kernel_launch(void* const* d_in, const int* in_sizes, int n_in,
                              void* d_out, int out_size)
{
    const float* f0   = (const float*)d_in[0];
    const float* f1   = (const float*)d_in[1];
    const float* f2   = (const float*)d_in[2];
    const float* f3   = (const float*)d_in[3];
    const float* rois = (const float*)d_in[4];
    const float* w1   = (const float*)d_in[5];
    const float* b1   = (const float*)d_in[6];
    const float* w2   = (const float*)d_in[7];
    const float* b2   = (const float*)d_in[8];
    const float* wb   = (const float*)d_in[9];
    const float* bb   = (const float*)d_in[10];
    const float* wc   = (const float*)d_in[11];
    const float* bc   = (const float*)d_in[12];
    const float* wr   = (const float*)d_in[13];
    const float* br   = (const float*)d_in[14];
    const float* wu   = (const float*)d_in[15];
    const float* bu   = (const float*)d_in[16];
    float* out = (float*)d_out;

    // weight conversions
    split_w<<<(DDIM * KDIM / 4 + 255) / 256, 256>>>((const float4*)w1, 0, DDIM * KDIM / 4);
    split_w<<<(DDIM * DDIM / 4 + 255) / 256, 256>>>((const float4*)w2, 1, DDIM * DDIM / 4);

    // RoIAlign -> fp16 A
    roi_align_kernel<<<NROIS, 192>>>(f0, f1, f2, f3, rois);

    // FC1: [1024,9408] @ [768,9408]^T, single-pass fp16, split-K=6 (49 chunks)
    gemm_fc1<<<dim3(MPAD / 128, DDIM / 128, KSPLIT1), 256>>>(KDIM / 32 / KSPLIT1);
    combine_bias_relu<<<(MN / 2 + 255) / 256, 256>>>(b1, 0, KSPLIT1);

    // FC2: [1024,768] @ [768,768]^T, 3-pass, split-K=3 (8 chunks)
    gemm_fc2<<<dim3(MPAD / 128, DDIM / 64, KSPLIT2), 256>>>(DDIM / 32 / KSPLIT2);
    combine_bias_relu<<<(MN / 2 + 255) / 256, 256>>>(b2, 1, KSPLIT2);

    heads_kernel<<<NROIS, 128>>>(wb, bb, wc, bc, wr, br, wu, bu, out);
}